// round 8
// baseline (speedup 1.0000x reference)
#include <cuda_runtime.h>
#include <cuda_bf16.h>
#include <math.h>

// Problem constants
#define BB 64
#define SS 512
#define EE 256
#define HH 512
#define G3 1536
#define TT 64
#define NCTA 128

// ---------------- device scratch ----------------
__device__ float g_gi[(size_t)SS * G3 * BB];       // [s][col][b]   201 MB
__device__ float g_states[(size_t)SS * BB * HH];   // [s][b][j]     64 MB
__device__ float4 g_h4[2][HH / 4][BB];             // [buf][k>>2][b] 256 KB
__device__ unsigned int g_bar;
__device__ int g_tok64;

// ---------------- f32x2 helpers ----------------
__device__ __forceinline__ unsigned long long ffma2(unsigned long long a,
                                                    unsigned long long b,
                                                    unsigned long long c) {
    unsigned long long d;
    asm("fma.rn.f32x2 %0, %1, %2, %3;" : "=l"(d) : "l"(a), "l"(b), "l"(c));
    return d;
}
__device__ __forceinline__ float2 unpack2(unsigned long long v) {
    float2 f;
    asm("mov.b64 {%0, %1}, %2;" : "=f"(f.x), "=f"(f.y) : "l"(v));
    return f;
}
__device__ __forceinline__ unsigned long long shfl_xor64(unsigned long long v, int m) {
    unsigned lo = (unsigned)v, hi = (unsigned)(v >> 32);
    lo = __shfl_xor_sync(0xffffffffu, lo, m);
    hi = __shfl_xor_sync(0xffffffffu, hi, m);
    return ((unsigned long long)hi << 32) | lo;
}
__device__ __forceinline__ unsigned long long add2(unsigned long long a, unsigned long long b) {
    unsigned long long d;
    asm("add.rn.f32x2 %0, %1, %2;" : "=l"(d) : "l"(a), "l"(b));
    return d;
}
__device__ __forceinline__ ulonglong2 ldcg_u2(const void* p) {
    ulonglong2 r;
    asm volatile("ld.global.cg.v2.u64 {%0, %1}, [%2];"
                 : "=l"(r.x), "=l"(r.y) : "l"(p));
    return r;
}
__device__ __forceinline__ int get_tok(const void* t, int i) {
    if (g_tok64) return (int)((const long long*)t)[i];
    return ((const int*)t)[i];
}
__device__ __forceinline__ float fast_sigmoid(float x) {
    return 1.0f / (1.0f + __expf(-x));
}
__device__ __forceinline__ float fast_tanh(float x) {
    return 1.0f - 2.0f / (__expf(2.0f * x) + 1.0f);
}

// ---------------- init ----------------
__global__ void init_kernel(const void* __restrict__ tokens) {
    int tid = blockIdx.x * blockDim.x + threadIdx.x;
    float* hz = (float*)g_h4;
    for (int i = tid; i < 2 * HH * BB; i += 64 * 256) hz[i] = 0.0f;
    if (blockIdx.x == 0 && threadIdx.x == 0) {
        g_bar = 0u;
        const long long* tt = (const long long*)tokens;
        int ok = 1;
        for (int i = 0; i < 128; i++) {
            long long v = tt[i];
            if (v < 0 || v >= 50000) { ok = 0; break; }
        }
        g_tok64 = ok;
    }
}

// ---------------- Phase 1: GI = emb[tok] @ W_ih^T + b_ih ----------------
__global__ __launch_bounds__(256) void gi_kernel(const void* __restrict__ tokens,
                                                 const float* __restrict__ emb,
                                                 const float* __restrict__ W_ih,
                                                 const float* __restrict__ b_ih) {
    __shared__ __align__(16) float As[64 * 36];
    __shared__ __align__(16) float Bs[128 * 36];
    __shared__ int toks[64];

    const int tid = threadIdx.x;
    const int s = blockIdx.y;
    const int colbase = blockIdx.x * 128;
    const int tx = tid & 15, ty = tid >> 4;
    const int ty4 = ty * 4, tx8 = tx * 8;

    if (tid < 64) toks[tid] = get_tok(tokens, tid * SS + s);
    __syncthreads();

    unsigned long long acc[4][8];
#pragma unroll
    for (int i = 0; i < 4; i++)
#pragma unroll
        for (int j = 0; j < 8; j++) acc[i][j] = 0ull;

    for (int k0 = 0; k0 < EE; k0 += 32) {
#pragma unroll
        for (int j = 0; j < 2; j++) {
            int f = tid * 2 + j;
            int r = f >> 3, kq = f & 7;
            float4 v = *(const float4*)(emb + (size_t)toks[r] * EE + k0 + kq * 4);
            *(float4*)&As[r * 36 + kq * 4] = v;
        }
#pragma unroll
        for (int j = 0; j < 4; j++) {
            int f = tid * 4 + j;
            int c = f >> 3, kq = f & 7;
            float4 v = *(const float4*)(W_ih + (size_t)(colbase + c) * EE + k0 + kq * 4);
            *(float4*)&Bs[c * 36 + kq * 4] = v;
        }
        __syncthreads();

#pragma unroll
        for (int k = 0; k < 32; k += 4) {
            ulonglong2 a2[4];
#pragma unroll
            for (int i = 0; i < 4; i++)
                a2[i] = *(const ulonglong2*)&As[(ty4 + i) * 36 + k];
#pragma unroll
            for (int j = 0; j < 8; j++) {
                ulonglong2 b2 = *(const ulonglong2*)&Bs[(tx8 + j) * 36 + k];
#pragma unroll
                for (int i = 0; i < 4; i++) {
                    acc[i][j] = ffma2(a2[i].x, b2.x, acc[i][j]);
                    acc[i][j] = ffma2(a2[i].y, b2.y, acc[i][j]);
                }
            }
        }
        __syncthreads();
    }

#pragma unroll
    for (int j = 0; j < 8; j++) {
        int col = colbase + tx8 + j;
        float bias = b_ih[col];
        size_t base = ((size_t)s * G3 + col) * BB;
#pragma unroll
        for (int i = 0; i < 4; i++) {
            float2 v = unpack2(acc[i][j]);
            g_gi[base + ty4 + i] = v.x + v.y + bias;
        }
    }
}

// ---------------- Phase 2: persistent GRU recurrence ----------------
// 128 CTAs x 256 thr. CTA owns 4 units (12 gh cols). lane = bl*4+kg.
// Weights smem k-major per col, skewed; k-pair accumulation (no pack MOVs).
__global__ __launch_bounds__(256, 1) void gru_kernel(const float* __restrict__ W_hh,
                                                     const float* __restrict__ b_hh) {
    __shared__ __align__(16) float w_s[12 * 532];  // [c][k] skewed, 25.5 KB
    __shared__ float bhh_s[12];

    const int tid = threadIdx.x;
    const int j0 = blockIdx.x * 4;
    const int warp = tid >> 5, lane = tid & 31;
    const int bl = lane >> 2, kg = lane & 3;
    const int b = warp * 8 + bl;

    // w_s[c][k] at c*532 + k + (k>>7)*4 ; c = gate*4+u
    for (int idx = tid; idx < 12 * HH; idx += 256) {
        int c = idx >> 9, k = idx & 511;
        int gate = c >> 2, u = c & 3;
        w_s[c * 532 + k + ((k >> 7) << 2)] =
            W_hh[(size_t)(gate * HH + j0 + u) * HH + k];
    }
    if (tid < 12) {
        int gate = tid >> 2, u = tid & 3;
        bhh_s[tid] = b_hh[gate * HH + j0 + u];
    }
    __syncthreads();

    const int kq0 = kg * 32;                    // float4-row range of this lane
    const float* wbase = w_s + kg * 132;        // kg*128 k-offset + kg*4 skew
    float hprev[4] = {0.f, 0.f, 0.f, 0.f};

    // gi for step 0 (prefetched; later steps prefetched before barrier wait)
    float gir[4], giz[4], gin[4];
    if (kg == 0) {
        const float* gis = g_gi;
#pragma unroll
        for (int u = 0; u < 4; u++) {
            gir[u] = __ldcs(gis + (size_t)(j0 + u) * BB + b);
            giz[u] = __ldcs(gis + (size_t)(HH + j0 + u) * BB + b);
            gin[u] = __ldcs(gis + (size_t)(2 * HH + j0 + u) * BB + b);
        }
    }

    for (int s = 0; s < SS; s++) {
        const int cur = s & 1, nxt = cur ^ 1;
        const float4* __restrict__ hc = &g_h4[cur][0][0];

        unsigned long long acc[12];
#pragma unroll
        for (int c = 0; c < 12; c++) acc[c] = 0ull;

        // pipelined h loads: 32 x 16B in groups of 8
        ulonglong2 hA[8], hB[8];
#pragma unroll
        for (int i = 0; i < 8; i++) hA[i] = ldcg_u2(&hc[(kq0 + i) * BB + b]);

#pragma unroll
        for (int g = 0; g < 4; g++) {
            if (g < 3) {
#pragma unroll
                for (int i = 0; i < 8; i++)
                    hB[i] = ldcg_u2(&hc[(kq0 + (g + 1) * 8 + i) * BB + b]);
            }
#pragma unroll
            for (int i = 0; i < 8; i++) {
                const int kk = (g * 8 + i) * 4;   // k within this kg's 128
                const ulonglong2 h2 = hA[i];      // (k01 pair, k23 pair)
#pragma unroll
                for (int c = 0; c < 12; c++) {
                    ulonglong2 w2 = *(const ulonglong2*)(wbase + c * 532 + kk);
                    acc[c] = ffma2(h2.x, w2.x, acc[c]);
                    acc[c] = ffma2(h2.y, w2.y, acc[c]);
                }
            }
            if (g < 3) {
#pragma unroll
                for (int i = 0; i < 8; i++) hA[i] = hB[i];
            }
        }

        // reduce across 4 k-split lanes (lane bits 0,1)
#pragma unroll
        for (int c = 0; c < 12; c++) {
            acc[c] = add2(acc[c], shfl_xor64(acc[c], 1));
            acc[c] = add2(acc[c], shfl_xor64(acc[c], 2));
        }

        if (kg == 0) {
            float gh[12];
#pragma unroll
            for (int c = 0; c < 12; c++) {
                float2 v = unpack2(acc[c]);
                gh[c] = v.x + v.y;
            }
            float hnew[4];
#pragma unroll
            for (int u = 0; u < 4; u++) {
                float r = fast_sigmoid(gir[u] + gh[u] + bhh_s[u]);
                float z = fast_sigmoid(giz[u] + gh[4 + u] + bhh_s[4 + u]);
                float n = fast_tanh(gin[u] + r * (gh[8 + u] + bhh_s[8 + u]));
                hnew[u] = (1.0f - z) * n + z * hprev[u];
            }
#pragma unroll
            for (int u = 0; u < 4; u++) hprev[u] = hnew[u];
            float4 hv4 = make_float4(hnew[0], hnew[1], hnew[2], hnew[3]);
            g_h4[nxt][j0 >> 2][b] = hv4;
            __stcs((float4*)(g_states + ((size_t)s * BB + b) * HH + j0), hv4);

            // prefetch next step's gi — latency hidden behind barrier wait
            if (s + 1 < SS) {
                const float* gis = g_gi + (size_t)(s + 1) * G3 * BB;
#pragma unroll
                for (int u = 0; u < 4; u++) {
                    gir[u] = __ldcs(gis + (size_t)(j0 + u) * BB + b);
                    giz[u] = __ldcs(gis + (size_t)(HH + j0 + u) * BB + b);
                    gin[u] = __ldcs(gis + (size_t)(2 * HH + j0 + u) * BB + b);
                }
            }
        }

        // ---- barrier v2: no full-CTA membar.gl ----
        __syncthreads();   // all CTA h-stores are program-ordered before release
        if (tid == 0) {
            unsigned one = 1u, v;
            asm volatile("red.release.gpu.global.add.u32 [%0], %1;"
                         :: "l"(&g_bar), "r"(one) : "memory");
            unsigned target = (unsigned)NCTA * (unsigned)(s + 1);
            do {
                asm volatile("ld.relaxed.gpu.global.u32 %0, [%1];"
                             : "=r"(v) : "l"(&g_bar) : "memory");
            } while (v < target);
            asm volatile("ld.acquire.gpu.global.u32 %0, [%1];"
                         : "=r"(v) : "l"(&g_bar) : "memory");
        }
        __syncthreads();
    }
}

// ---------------- pad: shifts the ncu -s5-c1 slot onto gru_kernel ----------------
__global__ void slotpad_kernel() {}

// ---------------- Phase 3: tag logits ----------------
__global__ __launch_bounds__(256) void tag_kernel(const float* __restrict__ W_tag,
                                                  const float* __restrict__ b_tag,
                                                  float* __restrict__ out) {
    __shared__ __align__(16) float As[64 * 36];
    __shared__ __align__(16) float Ws[64 * 36];

    const int tid = threadIdx.x;
    const int s = blockIdx.x;
    const int tx = tid & 15, ty = tid >> 4;
    const int b4 = ty * 4, t4 = tx * 4;

    unsigned long long acc[4][4];
#pragma unroll
    for (int i = 0; i < 4; i++)
#pragma unroll
        for (int j = 0; j < 4; j++) acc[i][j] = 0ull;

    for (int k0 = 0; k0 < HH; k0 += 32) {
#pragma unroll
        for (int j = 0; j < 2; j++) {
            int f = tid * 2 + j;
            int r = f >> 3, kq = f & 7;
            float4 v = *(const float4*)(g_states + ((size_t)s * BB + r) * HH + k0 + kq * 4);
            *(float4*)&As[r * 36 + kq * 4] = v;
            float4 w = *(const float4*)(W_tag + (size_t)r * HH + k0 + kq * 4);
            *(float4*)&Ws[r * 36 + kq * 4] = w;
        }
        __syncthreads();
#pragma unroll
        for (int k = 0; k < 32; k += 4) {
            ulonglong2 a2[4];
#pragma unroll
            for (int i = 0; i < 4; i++)
                a2[i] = *(const ulonglong2*)&As[(b4 + i) * 36 + k];
#pragma unroll
            for (int j = 0; j < 4; j++) {
                ulonglong2 w2 = *(const ulonglong2*)&Ws[(t4 + j) * 36 + k];
#pragma unroll
                for (int i = 0; i < 4; i++) {
                    acc[i][j] = ffma2(a2[i].x, w2.x, acc[i][j]);
                    acc[i][j] = ffma2(a2[i].y, w2.y, acc[i][j]);
                }
            }
        }
        __syncthreads();
    }

#pragma unroll
    for (int j = 0; j < 4; j++) {
        int t = t4 + j;
        float bias = b_tag[t];
#pragma unroll
        for (int i = 0; i < 4; i++) {
            int bb = b4 + i;
            float2 v = unpack2(acc[i][j]);
            out[((size_t)bb * SS + s) * TT + t] = v.x + v.y + bias;
        }
    }
}

// ---------------- Phase 4: masked argmax preds ----------------
__global__ void pred_kernel(const void* __restrict__ tokens,
                            float* __restrict__ out, int out_size) {
    const int i = blockIdx.x * blockDim.x + threadIdx.x;  // i = b*512 + s
    if (i >= BB * SS) return;
    const float* lg = out + (size_t)i * TT;
    float best = lg[0];
    int bi = 0;
#pragma unroll 8
    for (int t = 1; t < TT; t++) {
        float v = lg[t];
        if (v > best) { best = v; bi = t; }
    }
    int tk = get_tok(tokens, i);
    long long pred = (tk != 0) ? (long long)bi : 0ll;

    const int NLOGIT = BB * SS * TT;  // 2097152
    int rem = out_size - NLOGIT;
    if (rem >= 2 * BB * SS) {
        long long* po = (long long*)((char*)out + (size_t)NLOGIT * 4);
        po[i] = pred;
    } else if (rem >= BB * SS) {
        out[NLOGIT + i] = (float)pred;
    }
}

// ---------------- launch ----------------
extern "C" void kernel_launch(void* const* d_in, const int* in_sizes, int n_in,
                              void* d_out, int out_size) {
    const void* tokens = d_in[0];
    const float* emb = (const float*)d_in[1];
    const float* W_ih = (const float*)d_in[2];
    const float* W_hh = (const float*)d_in[3];
    const float* b_ih = (const float*)d_in[4];
    const float* b_hh = (const float*)d_in[5];
    const float* W_tag = (const float*)d_in[6];
    const float* b_tag = (const float*)d_in[7];
    float* out = (float*)d_out;

    init_kernel<<<64, 256>>>(tokens);
    gi_kernel<<<dim3(12, 512), 256>>>(tokens, emb, W_ih, b_ih);
    gru_kernel<<<NCTA, 256>>>(W_hh, b_hh);
    slotpad_kernel<<<1, 32>>>();
    tag_kernel<<<SS, 256>>>(W_tag, b_tag, out);
    pred_kernel<<<128, 256>>>(tokens, out, out_size);
}

// round 11
// speedup vs baseline: 1.1481x; 1.1481x over previous
#include <cuda_runtime.h>
#include <cuda_bf16.h>
#include <math.h>

// Problem constants
#define BB 64
#define SS 512
#define EE 256
#define HH 512
#define G3 1536
#define TT 64
#define NCTA 128

// ---------------- device scratch ----------------
__device__ float g_gi[(size_t)SS * BB * G3];       // [s][b][col]   201 MB
__device__ float g_states[(size_t)SS * BB * HH];   // [s][b][j]     64 MB
__device__ float4 g_h4[2][HH / 4][BB];             // [buf][k>>2][b] 256 KB
__device__ unsigned int g_bar;
__device__ int g_tok64;

// ---------------- f32x2 helpers ----------------
__device__ __forceinline__ unsigned long long ffma2(unsigned long long a,
                                                    unsigned long long b,
                                                    unsigned long long c) {
    unsigned long long d;
    asm("fma.rn.f32x2 %0, %1, %2, %3;" : "=l"(d) : "l"(a), "l"(b), "l"(c));
    return d;
}
__device__ __forceinline__ unsigned long long pack2(float lo, float hi) {
    unsigned long long r;
    asm("mov.b64 %0, {%1, %2};" : "=l"(r) : "f"(lo), "f"(hi));
    return r;
}
__device__ __forceinline__ float2 unpack2(unsigned long long v) {
    float2 f;
    asm("mov.b64 {%0, %1}, %2;" : "=f"(f.x), "=f"(f.y) : "l"(v));
    return f;
}
__device__ __forceinline__ unsigned long long shfl_xor64(unsigned long long v, int m) {
    unsigned lo = (unsigned)v, hi = (unsigned)(v >> 32);
    lo = __shfl_xor_sync(0xffffffffu, lo, m);
    hi = __shfl_xor_sync(0xffffffffu, hi, m);
    return ((unsigned long long)hi << 32) | lo;
}
__device__ __forceinline__ unsigned long long add2(unsigned long long a, unsigned long long b) {
    unsigned long long d;
    asm("add.rn.f32x2 %0, %1, %2;" : "=l"(d) : "l"(a), "l"(b));
    return d;
}
__device__ __forceinline__ int get_tok(const void* t, int i) {
    if (g_tok64) return (int)((const long long*)t)[i];
    return ((const int*)t)[i];
}
__device__ __forceinline__ float fast_sigmoid(float x) {
    return 1.0f / (1.0f + __expf(-x));
}
__device__ __forceinline__ float fast_tanh(float x) {
    return 1.0f - 2.0f / (__expf(2.0f * x) + 1.0f);
}

// ---------------- init ----------------
__global__ void init_kernel(const void* __restrict__ tokens) {
    int tid = blockIdx.x * blockDim.x + threadIdx.x;
    float* hz = (float*)g_h4;
    for (int i = tid; i < 2 * HH * BB; i += 64 * 256) hz[i] = 0.0f;
    if (blockIdx.x == 0 && threadIdx.x == 0) {
        g_bar = 0u;
        const long long* tt = (const long long*)tokens;
        int ok = 1;
        for (int i = 0; i < 128; i++) {
            long long v = tt[i];
            if (v < 0 || v >= 50000) { ok = 0; break; }
        }
        g_tok64 = ok;
    }
}

// ---------------- Phase 1: GI = emb[tok] @ W_ih^T + b_ih ----------------
// Output layout [s][b][col] -> coalesced 512B row stores per warp.
__global__ __launch_bounds__(256) void gi_kernel(const void* __restrict__ tokens,
                                                 const float* __restrict__ emb,
                                                 const float* __restrict__ W_ih,
                                                 const float* __restrict__ b_ih) {
    __shared__ __align__(16) float As[64 * 36];
    __shared__ __align__(16) float Bs[128 * 36];
    __shared__ int toks[64];

    const int tid = threadIdx.x;
    const int s = blockIdx.y;
    const int colbase = blockIdx.x * 128;
    const int tx = tid & 15, ty = tid >> 4;
    const int ty4 = ty * 4, tx8 = tx * 8;

    if (tid < 64) toks[tid] = get_tok(tokens, tid * SS + s);

    // biases for this thread's 8 cols (constant across k-loop)
    float bias[8];
#pragma unroll
    for (int j = 0; j < 8; j++) bias[j] = b_ih[colbase + tx8 + j];
    __syncthreads();

    unsigned long long acc[4][8];
#pragma unroll
    for (int i = 0; i < 4; i++)
#pragma unroll
        for (int j = 0; j < 8; j++) acc[i][j] = 0ull;

    for (int k0 = 0; k0 < EE; k0 += 32) {
#pragma unroll
        for (int j = 0; j < 2; j++) {
            int f = tid * 2 + j;
            int r = f >> 3, kq = f & 7;
            float4 v = *(const float4*)(emb + (size_t)toks[r] * EE + k0 + kq * 4);
            *(float4*)&As[r * 36 + kq * 4] = v;
        }
#pragma unroll
        for (int j = 0; j < 4; j++) {
            int f = tid * 4 + j;
            int c = f >> 3, kq = f & 7;
            float4 v = *(const float4*)(W_ih + (size_t)(colbase + c) * EE + k0 + kq * 4);
            *(float4*)&Bs[c * 36 + kq * 4] = v;
        }
        __syncthreads();

#pragma unroll
        for (int k = 0; k < 32; k += 4) {
            ulonglong2 a2[4];
#pragma unroll
            for (int i = 0; i < 4; i++)
                a2[i] = *(const ulonglong2*)&As[(ty4 + i) * 36 + k];
#pragma unroll
            for (int j = 0; j < 8; j++) {
                ulonglong2 b2 = *(const ulonglong2*)&Bs[(tx8 + j) * 36 + k];
#pragma unroll
                for (int i = 0; i < 4; i++) {
                    acc[i][j] = ffma2(a2[i].x, b2.x, acc[i][j]);
                    acc[i][j] = ffma2(a2[i].y, b2.y, acc[i][j]);
                }
            }
        }
        __syncthreads();
    }

    // coalesced store: [s][b][col], thread writes 2 float4 per batch row
#pragma unroll
    for (int i = 0; i < 4; i++) {
        float o[8];
#pragma unroll
        for (int j = 0; j < 8; j++) {
            float2 v = unpack2(acc[i][j]);
            o[j] = v.x + v.y + bias[j];
        }
        size_t base = ((size_t)s * BB + ty4 + i) * G3 + colbase + tx8;
        *(float4*)&g_gi[base]     = make_float4(o[0], o[1], o[2], o[3]);
        *(float4*)&g_gi[base + 4] = make_float4(o[4], o[5], o[6], o[7]);
    }
}

// ---------------- pad: shifts the profiled slot (4th launch) onto gru ----------------
__global__ void slotpad_kernel() {}

// ---------------- Phase 2: persistent GRU recurrence (R3-best form) ----------------
// 128 CTAs; CTA owns 4 hidden units (12 W_hh rows in smem as skewed [k][c]).
// lane = bl*4+kg: bl 0..7 (batch-in-warp), kg 0..3 (k-split, 128 k each).
#define WSKEW(k) ((k) * 12 + (((k) >> 7) << 2))
__global__ __launch_bounds__(256, 1) void gru_kernel(const float* __restrict__ W_hh,
                                                     const float* __restrict__ b_hh) {
    __shared__ __align__(16) float w_s[HH * 12 + 16];  // skewed [k][c]
    __shared__ float bhh_s[12];

    const int tid = threadIdx.x;
    const int j0 = blockIdx.x * 4;
    const int warp = tid >> 5, lane = tid & 31;
    const int bl = lane >> 2, kg = lane & 3;
    const int b = warp * 8 + bl;

    for (int idx = tid; idx < HH * 12; idx += 256) {
        int k = idx / 12, c = idx % 12;
        int gate = c >> 2, u = c & 3;
        w_s[WSKEW(k) + c] = W_hh[(size_t)(gate * HH + j0 + u) * HH + k];
    }
    if (tid < 12) {
        int gate = tid >> 2, u = tid & 3;
        bhh_s[tid] = b_hh[gate * HH + j0 + u];
    }
    __syncthreads();

    const int kq0 = kg * 32;
    const float* wbase = w_s + WSKEW(kg * 128);
    float hprev0 = 0.0f, hprev1 = 0.0f, hprev2 = 0.0f, hprev3 = 0.0f;

    for (int s = 0; s < SS; s++) {
        const int cur = s & 1, nxt = cur ^ 1;
        const float4* __restrict__ hc = &g_h4[cur][0][0];

        // gi loads for this step: 3 x LDG.128 (contiguous gates in [s][b][col])
        float4 gir4, giz4, gin4;
        if (kg == 0) {
            const float* gis = g_gi + ((size_t)s * BB + b) * G3 + j0;
            gir4 = __ldcs((const float4*)(gis));
            giz4 = __ldcs((const float4*)(gis + HH));
            gin4 = __ldcs((const float4*)(gis + 2 * HH));
        }

        unsigned long long acc[6] = {0ull, 0ull, 0ull, 0ull, 0ull, 0ull};

        // software-pipelined mainloop: 32 float4 h loads in groups of 8
        float4 hA[8], hB[8];
#pragma unroll
        for (int i = 0; i < 8; i++) hA[i] = __ldcg(&hc[(kq0 + i) * BB + b]);

#pragma unroll
        for (int g = 0; g < 4; g++) {
            if (g < 3) {
#pragma unroll
                for (int i = 0; i < 8; i++)
                    hB[i] = __ldcg(&hc[(kq0 + (g + 1) * 8 + i) * BB + b]);
            }
#pragma unroll
            for (int i = 0; i < 8; i++) {
                const float hv[4] = {hA[i].x, hA[i].y, hA[i].z, hA[i].w};
#pragma unroll
                for (int j = 0; j < 4; j++) {
                    int kk = (g * 8 + i) * 4 + j;
                    const ulonglong2* wp = (const ulonglong2*)(wbase + kk * 12);
                    unsigned long long h2 = pack2(hv[j], hv[j]);
                    ulonglong2 w0 = wp[0], w1 = wp[1], w2v = wp[2];
                    acc[0] = ffma2(h2, w0.x, acc[0]);
                    acc[1] = ffma2(h2, w0.y, acc[1]);
                    acc[2] = ffma2(h2, w1.x, acc[2]);
                    acc[3] = ffma2(h2, w1.y, acc[3]);
                    acc[4] = ffma2(h2, w2v.x, acc[4]);
                    acc[5] = ffma2(h2, w2v.y, acc[5]);
                }
            }
            if (g < 3) {
#pragma unroll
                for (int i = 0; i < 8; i++) hA[i] = hB[i];
            }
        }

        // reduce across the 4 k-split lanes
#pragma unroll
        for (int j = 0; j < 6; j++) {
            acc[j] = add2(acc[j], shfl_xor64(acc[j], 1));
            acc[j] = add2(acc[j], shfl_xor64(acc[j], 2));
        }

        if (kg == 0) {
            float gh[12];
#pragma unroll
            for (int j = 0; j < 6; j++) {
                float2 v = unpack2(acc[j]);
                gh[2 * j] = v.x;
                gh[2 * j + 1] = v.y;
            }
            const float gir[4] = {gir4.x, gir4.y, gir4.z, gir4.w};
            const float giz[4] = {giz4.x, giz4.y, giz4.z, giz4.w};
            const float gin[4] = {gin4.x, gin4.y, gin4.z, gin4.w};
            float hp[4] = {hprev0, hprev1, hprev2, hprev3};
            float hnew[4];
#pragma unroll
            for (int u = 0; u < 4; u++) {
                float r = fast_sigmoid(gir[u] + gh[u] + bhh_s[u]);
                float z = fast_sigmoid(giz[u] + gh[4 + u] + bhh_s[4 + u]);
                float n = fast_tanh(gin[u] + r * (gh[8 + u] + bhh_s[8 + u]));
                hnew[u] = (1.0f - z) * n + z * hp[u];
            }
            hprev0 = hnew[0]; hprev1 = hnew[1]; hprev2 = hnew[2]; hprev3 = hnew[3];
            float4 hv4 = make_float4(hnew[0], hnew[1], hnew[2], hnew[3]);
            g_h4[nxt][j0 >> 2][b] = hv4;
            __stcs((float4*)(g_states + ((size_t)s * BB + b) * HH + j0), hv4);
        }

        // grid barrier v1 (monotonic generation counter)
        __threadfence();
        __syncthreads();
        if (tid == 0) {
            unsigned target = (unsigned)NCTA * (unsigned)(s + 1);
            atomicAdd(&g_bar, 1u);
            unsigned v;
            do {
                asm volatile("ld.global.acquire.gpu.u32 %0, [%1];"
                             : "=r"(v) : "l"(&g_bar));
            } while (v < target);
        }
        __syncthreads();
    }
}

// ---------------- Phase 3: tag logits = states @ W_tag^T + b_tag ----------------
__global__ __launch_bounds__(256) void tag_kernel(const float* __restrict__ W_tag,
                                                  const float* __restrict__ b_tag,
                                                  float* __restrict__ out) {
    __shared__ __align__(16) float As[64 * 36];
    __shared__ __align__(16) float Ws[64 * 36];

    const int tid = threadIdx.x;
    const int s = blockIdx.x;
    const int tx = tid & 15, ty = tid >> 4;
    const int b4 = ty * 4, t4 = tx * 4;

    unsigned long long acc[4][4];
#pragma unroll
    for (int i = 0; i < 4; i++)
#pragma unroll
        for (int j = 0; j < 4; j++) acc[i][j] = 0ull;

    for (int k0 = 0; k0 < HH; k0 += 32) {
#pragma unroll
        for (int j = 0; j < 2; j++) {
            int f = tid * 2 + j;
            int r = f >> 3, kq = f & 7;
            float4 v = *(const float4*)(g_states + ((size_t)s * BB + r) * HH + k0 + kq * 4);
            *(float4*)&As[r * 36 + kq * 4] = v;
            float4 w = *(const float4*)(W_tag + (size_t)r * HH + k0 + kq * 4);
            *(float4*)&Ws[r * 36 + kq * 4] = w;
        }
        __syncthreads();
#pragma unroll
        for (int k = 0; k < 32; k += 4) {
            ulonglong2 a2[4];
#pragma unroll
            for (int i = 0; i < 4; i++)
                a2[i] = *(const ulonglong2*)&As[(b4 + i) * 36 + k];
#pragma unroll
            for (int j = 0; j < 4; j++) {
                ulonglong2 w2 = *(const ulonglong2*)&Ws[(t4 + j) * 36 + k];
#pragma unroll
                for (int i = 0; i < 4; i++) {
                    acc[i][j] = ffma2(a2[i].x, w2.x, acc[i][j]);
                    acc[i][j] = ffma2(a2[i].y, w2.y, acc[i][j]);
                }
            }
        }
        __syncthreads();
    }

#pragma unroll
    for (int j = 0; j < 4; j++) {
        int t = t4 + j;
        float bias = b_tag[t];
#pragma unroll
        for (int i = 0; i < 4; i++) {
            int bb = b4 + i;
            float2 v = unpack2(acc[i][j]);
            out[((size_t)bb * SS + s) * TT + t] = v.x + v.y + bias;
        }
    }
}

// ---------------- Phase 4: masked argmax preds ----------------
__global__ void pred_kernel(const void* __restrict__ tokens,
                            float* __restrict__ out, int out_size) {
    const int i = blockIdx.x * blockDim.x + threadIdx.x;  // i = b*512 + s
    if (i >= BB * SS) return;
    const float* lg = out + (size_t)i * TT;
    float best = lg[0];
    int bi = 0;
#pragma unroll 8
    for (int t = 1; t < TT; t++) {
        float v = lg[t];
        if (v > best) { best = v; bi = t; }
    }
    int tk = get_tok(tokens, i);
    long long pred = (tk != 0) ? (long long)bi : 0ll;

    const int NLOGIT = BB * SS * TT;  // 2097152
    int rem = out_size - NLOGIT;
    if (rem >= 2 * BB * SS) {
        long long* po = (long long*)((char*)out + (size_t)NLOGIT * 4);
        po[i] = pred;
    } else if (rem >= BB * SS) {
        out[NLOGIT + i] = (float)pred;
    }
}

// ---------------- launch ----------------
extern "C" void kernel_launch(void* const* d_in, const int* in_sizes, int n_in,
                              void* d_out, int out_size) {
    const void* tokens = d_in[0];
    const float* emb = (const float*)d_in[1];
    const float* W_ih = (const float*)d_in[2];
    const float* W_hh = (const float*)d_in[3];
    const float* b_ih = (const float*)d_in[4];
    const float* b_hh = (const float*)d_in[5];
    const float* W_tag = (const float*)d_in[6];
    const float* b_tag = (const float*)d_in[7];
    float* out = (float*)d_out;

    init_kernel<<<64, 256>>>(tokens);
    gi_kernel<<<dim3(12, 512), 256>>>(tokens, emb, W_ih, b_ih);
    slotpad_kernel<<<1, 32>>>();                       // gru becomes 4th launch
    gru_kernel<<<NCTA, 256>>>(W_hh, b_hh);
    tag_kernel<<<SS, 256>>>(W_tag, b_tag, out);
    pred_kernel<<<128, 256>>>(tokens, out, out_size);
}

// round 14
// speedup vs baseline: 1.4128x; 1.2305x over previous
#include <cuda_runtime.h>
#include <cuda_bf16.h>
#include <math.h>

// Problem constants
#define BB 64
#define SS 512
#define EE 256
#define HH 512
#define G3 1536
#define TT 64
#define NCTA 128

// ---------------- device scratch ----------------
__device__ float g_gi[(size_t)SS * BB * G3];       // [s][b][col]   201 MB
__device__ float g_states[(size_t)SS * BB * HH];   // [s][b][j]     64 MB
__device__ float g_h[2 * HH * BB];                 // [buf][k][b]   256 KB
__device__ unsigned int g_bar;
__device__ int g_tok64;

// ---------------- f32x2 helpers ----------------
__device__ __forceinline__ unsigned long long ffma2(unsigned long long a,
                                                    unsigned long long b,
                                                    unsigned long long c) {
    unsigned long long d;
    asm("fma.rn.f32x2 %0, %1, %2, %3;" : "=l"(d) : "l"(a), "l"(b), "l"(c));
    return d;
}
__device__ __forceinline__ unsigned long long pack2(float lo, float hi) {
    unsigned long long r;
    asm("mov.b64 %0, {%1, %2};" : "=l"(r) : "f"(lo), "f"(hi));
    return r;
}
__device__ __forceinline__ float2 unpack2(unsigned long long v) {
    float2 f;
    asm("mov.b64 {%0, %1}, %2;" : "=f"(f.x), "=f"(f.y) : "l"(v));
    return f;
}
__device__ __forceinline__ unsigned long long add2(unsigned long long a, unsigned long long b) {
    unsigned long long d;
    asm("add.rn.f32x2 %0, %1, %2;" : "=l"(d) : "l"(a), "l"(b));
    return d;
}
__device__ __forceinline__ int get_tok(const void* t, int i) {
    if (g_tok64) return (int)((const long long*)t)[i];
    return ((const int*)t)[i];
}
__device__ __forceinline__ float fast_sigmoid(float x) {
    return 1.0f / (1.0f + __expf(-x));
}
__device__ __forceinline__ float fast_tanh(float x) {
    return 1.0f - 2.0f / (__expf(2.0f * x) + 1.0f);
}

// ---------------- init ----------------
__global__ void init_kernel(const void* __restrict__ tokens) {
    int tid = blockIdx.x * blockDim.x + threadIdx.x;
    for (int i = tid; i < 2 * HH * BB; i += 64 * 256) g_h[i] = 0.0f;
    if (blockIdx.x == 0 && threadIdx.x == 0) {
        g_bar = 0u;
        const long long* tt = (const long long*)tokens;
        int ok = 1;
        for (int i = 0; i < 128; i++) {
            long long v = tt[i];
            if (v < 0 || v >= 50000) { ok = 0; break; }
        }
        g_tok64 = ok;
    }
}

// ---------------- Phase 1: GI = emb[tok] @ W_ih^T + b_ih ----------------
// Tile: 64 b x 128 cols, BK=32. smem transposed: As[k][b], Bs[k][c] so
// mainloop LDS reads are warp-uniform (As: 1 wf) / contiguous (Bs: 4 wf).
// f32x2 packs COL-PAIRS; A value duplicated via pack2.
__global__ __launch_bounds__(256) void gi_kernel(const void* __restrict__ tokens,
                                                 const float* __restrict__ emb,
                                                 const float* __restrict__ W_ih,
                                                 const float* __restrict__ b_ih) {
    __shared__ __align__(16) float As[32 * 68];    // [k][b], stride 68
    __shared__ __align__(16) float Bs[32 * 132];   // [k][c], stride 132
    __shared__ int toks[64];

    const int tid = threadIdx.x;
    const int s = blockIdx.y;
    const int colbase = blockIdx.x * 128;
    const int tx = tid & 15, ty = tid >> 4;
    const int ty4 = ty * 4, tx8 = tx * 8;

    if (tid < 64) toks[tid] = get_tok(tokens, tid * SS + s);

    float bias[8];
#pragma unroll
    for (int j = 0; j < 8; j++) bias[j] = b_ih[colbase + tx8 + j];
    __syncthreads();

    unsigned long long acc[4][4];   // [batch i][col-pair]
#pragma unroll
    for (int i = 0; i < 4; i++)
#pragma unroll
        for (int j = 0; j < 4; j++) acc[i][j] = 0ull;

    for (int k0 = 0; k0 < EE; k0 += 32) {
        // A: 64 b x 32 k, 2 float4/thread, transposed store
#pragma unroll
        for (int j = 0; j < 2; j++) {
            int f = tid * 2 + j;
            int r = f >> 3, kq = f & 7;
            float4 v = *(const float4*)(emb + (size_t)toks[r] * EE + k0 + kq * 4);
            As[(kq * 4 + 0) * 68 + r] = v.x;
            As[(kq * 4 + 1) * 68 + r] = v.y;
            As[(kq * 4 + 2) * 68 + r] = v.z;
            As[(kq * 4 + 3) * 68 + r] = v.w;
        }
        // B: 128 c x 32 k, 4 float4/thread, transposed store
#pragma unroll
        for (int j = 0; j < 4; j++) {
            int f = tid * 4 + j;
            int c = f >> 3, kq = f & 7;
            float4 v = *(const float4*)(W_ih + (size_t)(colbase + c) * EE + k0 + kq * 4);
            Bs[(kq * 4 + 0) * 132 + c] = v.x;
            Bs[(kq * 4 + 1) * 132 + c] = v.y;
            Bs[(kq * 4 + 2) * 132 + c] = v.z;
            Bs[(kq * 4 + 3) * 132 + c] = v.w;
        }
        __syncthreads();

#pragma unroll
        for (int k = 0; k < 32; k++) {
            float4 av = *(const float4*)&As[k * 68 + ty4];
            ulonglong2 b0 = *(const ulonglong2*)&Bs[k * 132 + tx8];
            ulonglong2 b1 = *(const ulonglong2*)&Bs[k * 132 + tx8 + 4];
            const float a4[4] = {av.x, av.y, av.z, av.w};
#pragma unroll
            for (int i = 0; i < 4; i++) {
                unsigned long long h2 = pack2(a4[i], a4[i]);
                acc[i][0] = ffma2(h2, b0.x, acc[i][0]);
                acc[i][1] = ffma2(h2, b0.y, acc[i][1]);
                acc[i][2] = ffma2(h2, b1.x, acc[i][2]);
                acc[i][3] = ffma2(h2, b1.y, acc[i][3]);
            }
        }
        __syncthreads();
    }

    // coalesced store: [s][b][col]
#pragma unroll
    for (int i = 0; i < 4; i++) {
        float o[8];
#pragma unroll
        for (int cp = 0; cp < 4; cp++) {
            float2 v = unpack2(acc[i][cp]);
            o[2 * cp] = v.x + bias[2 * cp];
            o[2 * cp + 1] = v.y + bias[2 * cp + 1];
        }
        size_t base = ((size_t)s * BB + ty4 + i) * G3 + colbase + tx8;
        *(float4*)&g_gi[base]     = make_float4(o[0], o[1], o[2], o[3]);
        *(float4*)&g_gi[base + 4] = make_float4(o[4], o[5], o[6], o[7]);
    }
}

// ---------------- pad: keeps gru as the profiled (4th) launch ----------------
__global__ void slotpad_kernel() {}

// ---------------- Phase 2: persistent GRU recurrence (warp-uniform weights) ----
// 128 CTAs x 8 warps. warp = bh(batch half: 32 b)*4 + wk(k-chunk: 128 k).
// lane = batch within half. Weight LDS.128 is warp-uniform -> 1 wavefront.
// Cross-warp k-reduction through smem; gates in warps wk==0.
__global__ __launch_bounds__(256, 1) void gru_kernel(const float* __restrict__ W_hh,
                                                     const float* __restrict__ b_hh) {
    __shared__ __align__(16) float w_s[HH * 12];                   // [k][c] 24 KB
    __shared__ __align__(16) unsigned long long red_s[8][32][6];   // 12 KB
    __shared__ float bhh_s[12];

    const int tid = threadIdx.x;
    const int j0 = blockIdx.x * 4;
    const int warp = tid >> 5, lane = tid & 31;
    const int wk = warp & 3, bh = warp >> 2;
    const int b = bh * 32 + lane;

    for (int idx = tid; idx < HH * 12; idx += 256) {
        int k = idx / 12, c = idx % 12;
        int gate = c >> 2, u = c & 3;
        w_s[idx] = W_hh[(size_t)(gate * HH + j0 + u) * HH + k];
    }
    if (tid < 12) {
        int gate = tid >> 2, u = tid & 3;
        bhh_s[tid] = b_hh[gate * HH + j0 + u];
    }
    __syncthreads();

    const float* wbase = w_s + wk * 128 * 12;
    float hprev[4] = {0.f, 0.f, 0.f, 0.f};

    for (int s = 0; s < SS; s++) {
        const int cur = s & 1, nxt = cur ^ 1;
        const float* __restrict__ hc = g_h + cur * (HH * BB) + wk * 128 * BB + b;

        // gi loads early (warps wk==0 only), hidden behind mainloop
        float4 gir4, giz4, gin4;
        if (wk == 0) {
            const float* gis = g_gi + ((size_t)s * BB + b) * G3 + j0;
            gir4 = __ldcs((const float4*)(gis));
            giz4 = __ldcs((const float4*)(gis + HH));
            gin4 = __ldcs((const float4*)(gis + 2 * HH));
        }

        unsigned long long acc[6] = {0ull, 0ull, 0ull, 0ull, 0ull, 0ull};

        // 128 k per warp; scalar coalesced h loads, double-buffered by 16
        float hbuf[16];
#pragma unroll
        for (int i = 0; i < 16; i++) hbuf[i] = __ldcg(hc + i * BB);

#pragma unroll
        for (int g = 0; g < 8; g++) {
            float hn[16];
            if (g < 7) {
#pragma unroll
                for (int i = 0; i < 16; i++)
                    hn[i] = __ldcg(hc + ((g + 1) * 16 + i) * BB);
            }
#pragma unroll
            for (int i = 0; i < 16; i++) {
                const int kl = g * 16 + i;
                unsigned long long h2 = pack2(hbuf[i], hbuf[i]);
                const ulonglong2* wp = (const ulonglong2*)(wbase + kl * 12);
                ulonglong2 w0 = wp[0], w1 = wp[1], w2 = wp[2];
                acc[0] = ffma2(h2, w0.x, acc[0]);
                acc[1] = ffma2(h2, w0.y, acc[1]);
                acc[2] = ffma2(h2, w1.x, acc[2]);
                acc[3] = ffma2(h2, w1.y, acc[3]);
                acc[4] = ffma2(h2, w2.x, acc[4]);
                acc[5] = ffma2(h2, w2.y, acc[5]);
            }
            if (g < 7) {
#pragma unroll
                for (int i = 0; i < 16; i++) hbuf[i] = hn[i];
            }
        }

        // stage partials from wk != 0 warps
        if (wk != 0) {
            ulonglong2* dst = (ulonglong2*)&red_s[warp][lane][0];
            dst[0] = make_ulonglong2(acc[0], acc[1]);
            dst[1] = make_ulonglong2(acc[2], acc[3]);
            dst[2] = make_ulonglong2(acc[4], acc[5]);
        }
        __syncthreads();

        if (wk == 0) {
#pragma unroll
            for (int w2i = 1; w2i < 4; w2i++) {
                const unsigned long long* src = &red_s[bh * 4 + w2i][lane][0];
#pragma unroll
                for (int c = 0; c < 6; c++) acc[c] = add2(acc[c], src[c]);
            }
            float gh[12];
#pragma unroll
            for (int c = 0; c < 6; c++) {
                float2 v = unpack2(acc[c]);
                gh[2 * c] = v.x;
                gh[2 * c + 1] = v.y;
            }
            const float gir[4] = {gir4.x, gir4.y, gir4.z, gir4.w};
            const float giz[4] = {giz4.x, giz4.y, giz4.z, giz4.w};
            const float gin[4] = {gin4.x, gin4.y, gin4.z, gin4.w};
            float hnew[4];
#pragma unroll
            for (int u = 0; u < 4; u++) {
                float r = fast_sigmoid(gir[u] + gh[u] + bhh_s[u]);
                float z = fast_sigmoid(giz[u] + gh[4 + u] + bhh_s[4 + u]);
                float n = fast_tanh(gin[u] + r * (gh[8 + u] + bhh_s[8 + u]));
                hnew[u] = (1.0f - z) * n + z * hprev[u];
                hprev[u] = hnew[u];
            }
            float* hnx = g_h + nxt * (HH * BB);
#pragma unroll
            for (int u = 0; u < 4; u++) hnx[(j0 + u) * BB + b] = hnew[u];
            __stcs((float4*)(g_states + ((size_t)s * BB + b) * HH + j0),
                   make_float4(hnew[0], hnew[1], hnew[2], hnew[3]));
        }

        // grid barrier v1 (monotonic generation counter)
        __threadfence();
        __syncthreads();
        if (tid == 0) {
            unsigned target = (unsigned)NCTA * (unsigned)(s + 1);
            atomicAdd(&g_bar, 1u);
            unsigned v;
            do {
                asm volatile("ld.global.acquire.gpu.u32 %0, [%1];"
                             : "=r"(v) : "l"(&g_bar));
            } while (v < target);
        }
        __syncthreads();
    }
}

// ---------------- Phase 3: tag logits = states @ W_tag^T + b_tag ----------------
__global__ __launch_bounds__(256) void tag_kernel(const float* __restrict__ W_tag,
                                                  const float* __restrict__ b_tag,
                                                  float* __restrict__ out) {
    __shared__ __align__(16) float As[64 * 36];
    __shared__ __align__(16) float Ws[64 * 36];

    const int tid = threadIdx.x;
    const int s = blockIdx.x;
    const int tx = tid & 15, ty = tid >> 4;
    const int b4 = ty * 4, t4 = tx * 4;

    unsigned long long acc[4][4];
#pragma unroll
    for (int i = 0; i < 4; i++)
#pragma unroll
        for (int j = 0; j < 4; j++) acc[i][j] = 0ull;

    for (int k0 = 0; k0 < HH; k0 += 32) {
#pragma unroll
        for (int j = 0; j < 2; j++) {
            int f = tid * 2 + j;
            int r = f >> 3, kq = f & 7;
            float4 v = *(const float4*)(g_states + ((size_t)s * BB + r) * HH + k0 + kq * 4);
            *(float4*)&As[r * 36 + kq * 4] = v;
            float4 w = *(const float4*)(W_tag + (size_t)r * HH + k0 + kq * 4);
            *(float4*)&Ws[r * 36 + kq * 4] = w;
        }
        __syncthreads();
#pragma unroll
        for (int k = 0; k < 32; k += 4) {
            ulonglong2 a2[4];
#pragma unroll
            for (int i = 0; i < 4; i++)
                a2[i] = *(const ulonglong2*)&As[(b4 + i) * 36 + k];
#pragma unroll
            for (int j = 0; j < 4; j++) {
                ulonglong2 w2 = *(const ulonglong2*)&Ws[(t4 + j) * 36 + k];
#pragma unroll
                for (int i = 0; i < 4; i++) {
                    acc[i][j] = ffma2(a2[i].x, w2.x, acc[i][j]);
                    acc[i][j] = ffma2(a2[i].y, w2.y, acc[i][j]);
                }
            }
        }
        __syncthreads();
    }

#pragma unroll
    for (int j = 0; j < 4; j++) {
        int t = t4 + j;
        float bias = b_tag[t];
#pragma unroll
        for (int i = 0; i < 4; i++) {
            int bb = b4 + i;
            float2 v = unpack2(acc[i][j]);
            out[((size_t)bb * SS + s) * TT + t] = v.x + v.y + bias;
        }
    }
}

// ---------------- Phase 4: masked argmax preds ----------------
__global__ void pred_kernel(const void* __restrict__ tokens,
                            float* __restrict__ out, int out_size) {
    const int i = blockIdx.x * blockDim.x + threadIdx.x;  // i = b*512 + s
    if (i >= BB * SS) return;
    const float* lg = out + (size_t)i * TT;
    float best = lg[0];
    int bi = 0;
#pragma unroll 8
    for (int t = 1; t < TT; t++) {
        float v = lg[t];
        if (v > best) { best = v; bi = t; }
    }
    int tk = get_tok(tokens, i);
    long long pred = (tk != 0) ? (long long)bi : 0ll;

    const int NLOGIT = BB * SS * TT;  // 2097152
    int rem = out_size - NLOGIT;
    if (rem >= 2 * BB * SS) {
        long long* po = (long long*)((char*)out + (size_t)NLOGIT * 4);
        po[i] = pred;
    } else if (rem >= BB * SS) {
        out[NLOGIT + i] = (float)pred;
    }
}

// ---------------- launch ----------------
extern "C" void kernel_launch(void* const* d_in, const int* in_sizes, int n_in,
                              void* d_out, int out_size) {
    const void* tokens = d_in[0];
    const float* emb = (const float*)d_in[1];
    const float* W_ih = (const float*)d_in[2];
    const float* W_hh = (const float*)d_in[3];
    const float* b_ih = (const float*)d_in[4];
    const float* b_hh = (const float*)d_in[5];
    const float* W_tag = (const float*)d_in[6];
    const float* b_tag = (const float*)d_in[7];
    float* out = (float*)d_out;

    init_kernel<<<64, 256>>>(tokens);
    gi_kernel<<<dim3(12, 512), 256>>>(tokens, emb, W_ih, b_ih);
    slotpad_kernel<<<1, 32>>>();                       // gru stays 4th launch
    gru_kernel<<<NCTA, 256>>>(W_hh, b_hh);
    tag_kernel<<<SS, 256>>>(W_tag, b_tag, out);
    pred_kernel<<<128, 256>>>(tokens, out, out_size);
}